// round 13
// baseline (speedup 1.0000x reference)
#include <cuda_runtime.h>
#include <cuda_bf16.h>
#include <cstdint>

#define BB 32
#define CC 512
#define NN 1024
#define CQ 64
#define MR 640

// ---------------- scratch (device globals; no cudaMalloc) ----------------
__device__ float g_scale[3];
__device__ float g_bcat[MR];
__device__ __align__(16) __nv_bfloat16 g_w2h[MR * CC];
__device__ __align__(16) __nv_bfloat16 g_w2l[MR * CC];
__device__ __align__(16) __nv_bfloat16 g_xTh[(size_t)BB * NN * CC];
__device__ __align__(16) __nv_bfloat16 g_xTl[(size_t)BB * NN * CC];
__device__ __align__(16) __nv_bfloat16 g_qTh[(size_t)BB * NN * CQ];
__device__ __align__(16) __nv_bfloat16 g_qTl[(size_t)BB * NN * CQ];
__device__ __align__(16) __nv_bfloat16 g_kTh[(size_t)BB * NN * CQ];
__device__ __align__(16) __nv_bfloat16 g_kTl[(size_t)BB * NN * CQ];
__device__ __align__(16) __nv_bfloat16 g_vh [(size_t)BB * CC * NN];
__device__ __align__(16) __nv_bfloat16 g_pTh[(size_t)BB * NN * NN];
__device__ float g_csum[BB * NN];

// ---------------- helpers ----------------
__device__ __forceinline__ uint32_t smem_u32(const void* p) {
    uint32_t a;
    asm("{ .reg .u64 t; cvta.to.shared.u64 t, %1; cvt.u32.u64 %0, t; }" : "=r"(a) : "l"(p));
    return a;
}
__device__ __forceinline__ void cp16(uint32_t s, const void* g) {
    asm volatile("cp.async.cg.shared.global [%0], [%1], 16;" :: "r"(s), "l"(g));
}
__device__ __forceinline__ void cp_commit() { asm volatile("cp.async.commit_group;" ::: "memory"); }
__device__ __forceinline__ void cp_wait1()  { asm volatile("cp.async.wait_group 1;" ::: "memory"); }
__device__ __forceinline__ void cp_wait0()  { asm volatile("cp.async.wait_group 0;" ::: "memory"); }

__device__ __forceinline__ void ldsm4(uint32_t r[4], uint32_t addr) {
    asm volatile("ldmatrix.sync.aligned.m8n8.x4.shared.b16 {%0,%1,%2,%3}, [%4];"
        : "=r"(r[0]), "=r"(r[1]), "=r"(r[2]), "=r"(r[3]) : "r"(addr));
}

__device__ __forceinline__ void mma16816(float* c, const uint32_t a[4], uint32_t b0, uint32_t b1) {
    asm volatile(
        "mma.sync.aligned.m16n8k16.row.col.f32.bf16.bf16.f32 "
        "{%0,%1,%2,%3}, {%4,%5,%6,%7}, {%8,%9}, {%0,%1,%2,%3};"
        : "+f"(c[0]), "+f"(c[1]), "+f"(c[2]), "+f"(c[3])
        : "r"(a[0]), "r"(a[1]), "r"(a[2]), "r"(a[3]), "r"(b0), "r"(b1));
}

__device__ __forceinline__ void split2(float f, __nv_bfloat16& h, __nv_bfloat16& l) {
    h = __float2bfloat16(f);
    l = __float2bfloat16(f - __bfloat162float(h));
}
__device__ __forceinline__ uint32_t packbf(__nv_bfloat16 a, __nv_bfloat16 b) {
    __nv_bfloat162 t(a, b);
    return *reinterpret_cast<uint32_t*>(&t);
}

// ---------------- generic GEMM core: 128x128 tile, K-chunk 32 ----------------
// P = pass count: 3 = (Ah+Al)*Bh + Ah*Bl ; 2 = (Ah+Al)*Bh
// Arrays: 128 rows x 32 bf16, stride 80 B -> conflict-free LDSM.
#define ARR_B   10240u
#define SMEM_QKP (2u * 4u * ARR_B)   // 81920: proj_qk / QK (P=3, S=2)
#define SMEM_PV  (3u * 3u * ARR_B)   // 92160: proj_v (P=2, S=3)

template<int P>
__device__ __forceinline__ void issue_chunk(uint32_t su, int stage,
        const __nv_bfloat16* Ah, const __nv_bfloat16* Al, int lda,
        const __nv_bfloat16* Bh, const __nv_bfloat16* Bl, int ldb,
        int koff, int tid) {
    const uint32_t STG  = (P == 3 ? 4u : 3u) * ARR_B;
    const uint32_t OFFB = 2u * ARR_B;
    uint32_t sb = su + (uint32_t)stage * STG;
    int row = tid >> 2, seg = tid & 3;
    uint32_t so  = (uint32_t)(row * 80 + seg * 16);
    uint32_t so2 = (uint32_t)((row + 64) * 80 + seg * 16);
    size_t go  = (size_t)row * lda + koff + seg * 8;
    size_t go2 = (size_t)(row + 64) * lda + koff + seg * 8;
    cp16(sb + so,  Ah + go);
    cp16(sb + so2, Ah + go2);
    cp16(sb + ARR_B + so,  Al + go);
    cp16(sb + ARR_B + so2, Al + go2);
    size_t gb  = (size_t)row * ldb + koff + seg * 8;
    size_t gb2 = (size_t)(row + 64) * ldb + koff + seg * 8;
    cp16(sb + OFFB + so,  Bh + gb);
    cp16(sb + OFFB + so2, Bh + gb2);
    if (P == 3) {
        cp16(sb + OFFB + ARR_B + so,  Bl + gb);
        cp16(sb + OFFB + ARR_B + so2, Bl + gb2);
    }
    cp_commit();
}

template<int P>
__device__ __forceinline__ void compute_chunk(uint32_t su, int stage,
        int wm, int wn, int lane, float acc[4][4][4]) {
    const uint32_t STG  = (P == 3 ? 4u : 3u) * ARR_B;
    const uint32_t OFFB = 2u * ARR_B;
    uint32_t sb = su + (uint32_t)stage * STG;
    int j = lane >> 3, r7 = lane & 7;
    uint32_t Ab = sb + (uint32_t)((wm * 64 + (j & 1) * 8 + r7) * 80 + (j >> 1) * 16);
    uint32_t Bb = sb + OFFB + (uint32_t)((wn * 32 + (j >> 1) * 8 + r7) * 80 + (j & 1) * 16);
    #pragma unroll
    for (int kk = 0; kk < 2; kk++) {
        uint32_t ko = (uint32_t)(kk * 32);
        uint32_t ah[4][4], al[4][4], bh[2][4], bl[2][4];
        #pragma unroll
        for (int mt = 0; mt < 4; mt++) ldsm4(ah[mt], Ab + (uint32_t)(mt * 1280) + ko);
        #pragma unroll
        for (int mt = 0; mt < 4; mt++) ldsm4(al[mt], Ab + ARR_B + (uint32_t)(mt * 1280) + ko);
        #pragma unroll
        for (int np = 0; np < 2; np++) ldsm4(bh[np], Bb + (uint32_t)(np * 1280) + ko);
        if (P == 3) {
            #pragma unroll
            for (int np = 0; np < 2; np++) ldsm4(bl[np], Bb + ARR_B + (uint32_t)(np * 1280) + ko);
        }
        #pragma unroll
        for (int mt = 0; mt < 4; mt++)
            #pragma unroll
            for (int nt = 0; nt < 4; nt++) {
                int np = nt >> 1, o = (nt & 1) * 2;
                float* C = acc[mt][nt];
                mma16816(C, ah[mt], bh[np][o], bh[np][o + 1]);
                mma16816(C, al[mt], bh[np][o], bh[np][o + 1]);
                if (P == 3) mma16816(C, ah[mt], bl[np][o], bl[np][o + 1]);
            }
    }
}

// Single-sync multistage mainloop.
template<int P, int S>
__device__ __forceinline__ void run_gemm(uint32_t su,
        const __nv_bfloat16* Ah, const __nv_bfloat16* Al, int lda,
        const __nv_bfloat16* Bh, const __nv_bfloat16* Bl, int ldb,
        int nch, float acc[4][4][4]) {
    int tid = threadIdx.x, lane = tid & 31, wid = tid >> 5;
    int wm = wid >> 2, wn = wid & 3;
    #pragma unroll
    for (int i = 0; i < 4; i++)
        #pragma unroll
        for (int j = 0; j < 4; j++)
            #pragma unroll
            for (int e = 0; e < 4; e++) acc[i][j][e] = 0.f;

    #pragma unroll
    for (int s = 0; s < S - 1; s++)
        issue_chunk<P>(su, s, Ah, Al, lda, Bh, Bl, ldb, s * 32, tid);

    for (int ch = 0; ch < nch; ch++) {
        if (S == 2) { cp_wait0(); }
        else        { if (ch == nch - 1) cp_wait0(); else cp_wait1(); }
        __syncthreads();
        int nx = ch + S - 1;
        if (nx < nch)
            issue_chunk<P>(su, nx % S, Ah, Al, lda, Bh, Bl, ldb, nx * 32, tid);
        compute_chunk<P>(su, ch % S, wm, wn, lane, acc);
    }
    __syncthreads();
}

// Stage one 64-row half of the 128x128 fp32 result into smem (stride 132).
__device__ __forceinline__ void stage_half(float* fb, int h, float acc[4][4][4]) {
    int tid = threadIdx.x, lane = tid & 31, wid = tid >> 5;
    int wm = wid >> 2, wn = wid & 3;
    if (wm != h) return;
    int g = lane >> 2, t = lane & 3;
    #pragma unroll
    for (int mt = 0; mt < 4; mt++)
        #pragma unroll
        for (int nt = 0; nt < 4; nt++) {
            float* p = fb + (mt * 16 + g) * 132 + wn * 32 + nt * 8 + 2 * t;
            p[0] = acc[mt][nt][0]; p[1] = acc[mt][nt][1];
            p[8 * 132] = acc[mt][nt][2]; p[8 * 132 + 1] = acc[mt][nt][3];
        }
}

// =================================================================
// Spectral norm (fp32)
// =================================================================
__global__ void spectral_k(const float* __restrict__ Wq, const float* __restrict__ uq,
                           const float* __restrict__ Wk, const float* __restrict__ uk,
                           const float* __restrict__ Wv, const float* __restrict__ uv) {
    const float* W; const float* u; int out;
    if (blockIdx.x == 0)      { W = Wq; u = uq; out = CQ; }
    else if (blockIdx.x == 1) { W = Wk; u = uk; out = CQ; }
    else                      { W = Wv; u = uv; out = CC; }
    const int in = CC;
    __shared__ float sv[CC];
    __shared__ float st[CC];
    __shared__ float red[16];
    int tid = threadIdx.x, lane = tid & 31, w = tid >> 5;

    float acc = 0.f;
    for (int i = 0; i < out; i++) acc += W[i * in + tid] * u[i];
    sv[tid] = acc;

    float s = acc * acc;
    #pragma unroll
    for (int o = 16; o; o >>= 1) s += __shfl_xor_sync(0xffffffffu, s, o);
    if (lane == 0) red[w] = s;
    __syncthreads();
    if (tid < 16) {
        float r = red[tid];
        #pragma unroll
        for (int o = 8; o; o >>= 1) r += __shfl_xor_sync(0xffffu, r, o);
        if (tid == 0) red[0] = r;
    }
    __syncthreads();
    float inv = rsqrtf(red[0]);
    __syncthreads();

    for (int i = w; i < out; i += 16) {
        float a = 0.f;
        for (int jj = lane; jj < in; jj += 32) a += W[i * in + jj] * sv[jj];
        #pragma unroll
        for (int o = 16; o; o >>= 1) a += __shfl_xor_sync(0xffffffffu, a, o);
        if (lane == 0) st[i] = a * inv;
    }
    __syncthreads();

    float q = (tid < out) ? st[tid] * st[tid] : 0.f;
    #pragma unroll
    for (int o = 16; o; o >>= 1) q += __shfl_xor_sync(0xffffffffu, q, o);
    if (lane == 0) red[w] = q;
    __syncthreads();
    if (tid == 0) {
        float r = 0.f;
        #pragma unroll
        for (int i = 0; i < 16; i++) r += red[i];
        g_scale[blockIdx.x] = rsqrtf(r);
    }
}

// =================================================================
// prep: fused build_w2k + xsplit (+ zero csum).
// grid (32, 16, 32), block (32, 8). First 1280 flat blocks also build weights.
// =================================================================
__global__ void prep_k(const float* __restrict__ x,
                       const float* __restrict__ Wq, const float* __restrict__ bq,
                       const float* __restrict__ Wk, const float* __restrict__ bk,
                       const float* __restrict__ Wv, const float* __restrict__ bv) {
    int tx = threadIdx.x, ty = threadIdx.y;
    int tid = ty * 32 + tx;
    int flat = (blockIdx.z * 16 + blockIdx.y) * 32 + blockIdx.x;

    // ---- weight build part (first 1280 blocks cover 640*512 elements) ----
    if (flat < (MR * CC) / 256) {
        int idx = flat * 256 + tid;
        if (idx < BB * NN) g_csum[idx] = 0.f;
        int r = idx >> 9, c = idx & (CC - 1);
        float wv, sc;
        if (r < CQ)          { wv = Wq[r * CC + c];            sc = g_scale[0]; }
        else if (r < 2 * CQ) { wv = Wk[(r - CQ) * CC + c];     sc = g_scale[1]; }
        else                 { wv = Wv[(r - 2 * CQ) * CC + c]; sc = g_scale[2]; }
        __nv_bfloat16 h, l;
        split2(wv * sc, h, l);
        g_w2h[idx] = h; g_w2l[idx] = l;
        if (c == 0)
            g_bcat[r] = (r < CQ) ? bq[r] : (r < 2 * CQ ? bk[r - CQ] : bv[r - 2 * CQ]);
    }

    // ---- xsplit part ----
    __shared__ float t[32][33];
    int b = blockIdx.z, n0 = blockIdx.x * 32, c0 = blockIdx.y * 32;
    const float* xb = x + (size_t)b * CC * NN;
    #pragma unroll
    for (int j = 0; j < 4; j++)
        t[ty + 8 * j][tx] = xb[(size_t)(c0 + ty + 8 * j) * NN + n0 + tx];
    __syncthreads();
    #pragma unroll
    for (int j = 0; j < 4; j++) {
        int n = n0 + ty + 8 * j;
        __nv_bfloat16 h, l;
        split2(t[tx][ty + 8 * j], h, l);
        size_t o = ((size_t)b * NN + n) * CC + c0 + tx;
        g_xTh[o] = h; g_xTl[o] = l;
    }
}

// =================================================================
// proj_qk (P=3,S=2): D[n][r] = xT[n]·w[r] + b[r] -> qT/kT hi/lo [b][n][64]
// =================================================================
__global__ __launch_bounds__(256, 2)
void proj_qk_mma(void) {
    extern __shared__ __align__(16) char sm[];
    uint32_t su = smem_u32(sm);
    int b = blockIdx.z, n0 = blockIdx.x * 128;
    const __nv_bfloat16* Ah = g_xTh + ((size_t)b * NN + n0) * CC;
    const __nv_bfloat16* Al = g_xTl + ((size_t)b * NN + n0) * CC;
    float acc[4][4][4];
    run_gemm<3, 2>(su, Ah, Al, CC, g_w2h, g_w2l, CC, CC / 32, acc);

    float* fb = (float*)sm;
    int tid = threadIdx.x, lane = tid & 31;
    for (int h = 0; h < 2; h++) {
        __syncthreads();
        stage_half(fb, h, acc);
        __syncthreads();
        #pragma unroll
        for (int j = 0; j < 8; j++) {
            int r = (tid >> 5) + j * 8;
            int n = n0 + h * 64 + r;
            int rr = lane * 4;
            const float* p = fb + r * 132 + rr;
            uint32_t hp[2], lp[2];
            #pragma unroll
            for (int e = 0; e < 2; e++) {
                float f0 = p[2 * e]     + g_bcat[rr + 2 * e];
                float f1 = p[2 * e + 1] + g_bcat[rr + 2 * e + 1];
                __nv_bfloat16 h0, l0, h1, l1;
                split2(f0, h0, l0); split2(f1, h1, l1);
                hp[e] = packbf(h0, h1); lp[e] = packbf(l0, l1);
            }
            size_t o;
            __nv_bfloat16 *dh, *dl;
            if (rr < 64) { o = ((size_t)b * NN + n) * CQ + rr;      dh = g_qTh; dl = g_qTl; }
            else         { o = ((size_t)b * NN + n) * CQ + rr - 64; dh = g_kTh; dl = g_kTl; }
            *reinterpret_cast<uint2*>(dh + o) = *reinterpret_cast<uint2*>(hp);
            *reinterpret_cast<uint2*>(dl + o) = *reinterpret_cast<uint2*>(lp);
        }
    }
}

// =================================================================
// proj_v (P=2,S=3): D[c][n] = (wh+wl)[c]·xh[n] + bv[c] -> v bf16 [b][c][n]
// =================================================================
__global__ __launch_bounds__(256, 2)
void proj_v_mma(void) {
    extern __shared__ __align__(16) char sm[];
    uint32_t su = smem_u32(sm);
    int b = blockIdx.z, n0 = blockIdx.x * 128, c0 = blockIdx.y * 128;
    const __nv_bfloat16* Ah = g_w2h + (size_t)(2 * CQ + c0) * CC;
    const __nv_bfloat16* Al = g_w2l + (size_t)(2 * CQ + c0) * CC;
    const __nv_bfloat16* Bh = g_xTh + ((size_t)b * NN + n0) * CC;
    float acc[4][4][4];
    run_gemm<2, 3>(su, Ah, Al, CC, Bh, (const __nv_bfloat16*)0, CC, CC / 32, acc);

    float* fb = (float*)sm;
    int tid = threadIdx.x, lane = tid & 31;
    for (int h = 0; h < 2; h++) {
        __syncthreads();
        stage_half(fb, h, acc);
        __syncthreads();
        #pragma unroll
        for (int j = 0; j < 8; j++) {
            int r = (tid >> 5) + j * 8;
            int c = c0 + h * 64 + r;
            float bias = g_bcat[2 * CQ + c];
            const float* p = fb + r * 132 + lane * 4;
            uint32_t hp[2];
            #pragma unroll
            for (int e = 0; e < 2; e++) {
                __nv_bfloat16 h0 = __float2bfloat16(p[2 * e] + bias);
                __nv_bfloat16 h1 = __float2bfloat16(p[2 * e + 1] + bias);
                hp[e] = packbf(h0, h1);
            }
            size_t o = ((size_t)b * CC + c) * NN + n0 + lane * 4;
            *reinterpret_cast<uint2*>(g_vh + o) = *reinterpret_cast<uint2*>(hp);
        }
    }
}

// =================================================================
// QK (P=3,S=2): D[m][n] = kT[m]·qT[n]; pT = bf16(exp(D)); csum += rounded sums
// =================================================================
__global__ __launch_bounds__(256, 2)
void gemm_qk_mma(void) {
    extern __shared__ __align__(16) char sm[];
    uint32_t su = smem_u32(sm);
    int b = blockIdx.z, m0 = blockIdx.y * 128, n0 = blockIdx.x * 128;
    const __nv_bfloat16* Ah = g_kTh + ((size_t)b * NN + m0) * CQ;
    const __nv_bfloat16* Al = g_kTl + ((size_t)b * NN + m0) * CQ;
    const __nv_bfloat16* Bh = g_qTh + ((size_t)b * NN + n0) * CQ;
    const __nv_bfloat16* Bl = g_qTl + ((size_t)b * NN + n0) * CQ;
    float acc[4][4][4];
    run_gemm<3, 2>(su, Ah, Al, CQ, Bh, Bl, CQ, CQ / 32, acc);

    float* fb = (float*)sm;
    int tid = threadIdx.x, lane = tid & 31;
    for (int h = 0; h < 2; h++) {
        __syncthreads();
        stage_half(fb, h, acc);
        __syncthreads();
        #pragma unroll
        for (int j = 0; j < 8; j++) {
            int r = (tid >> 5) + j * 8;       // whole warp shares row r
            int m = m0 + h * 64 + r;
            const float* p = fb + r * 132 + lane * 4;
            uint32_t hp[2];
            float rs = 0.f;
            #pragma unroll
            for (int e = 0; e < 2; e++) {
                __nv_bfloat16 h0 = __float2bfloat16(__expf(p[2 * e]));
                __nv_bfloat16 h1 = __float2bfloat16(__expf(p[2 * e + 1]));
                rs += __bfloat162float(h0) + __bfloat162float(h1);
                hp[e] = packbf(h0, h1);
            }
            size_t o = ((size_t)b * NN + m) * NN + n0 + lane * 4;
            *reinterpret_cast<uint2*>(g_pTh + o) = *reinterpret_cast<uint2*>(hp);
            #pragma unroll
            for (int of = 16; of; of >>= 1) rs += __shfl_xor_sync(0xffffffffu, rs, of);
            if (lane == 0) atomicAdd(&g_csum[b * NN + m], rs);
        }
    }
}

// =================================================================
// AV: 512 threads, tile 256(c) x 128(m), K-chunk 64, S=2, P=1.
// Warp grid 4x4, warp tile 64x32. Row stride 144 B (conflict-free LDSM).
// Fuses cinv = 1/csum (computed per-CTA into smem).
// =================================================================
#define AV_RS   144u
#define AV_AB   (256u * AV_RS)            // 36864
#define AV_STG  (AV_AB + 128u * AV_RS)    // 55296
#define SMEM_AVN (2u * AV_STG + 512u)     // 111104

__device__ __forceinline__ void av_issue(uint32_t su, int stage,
        const __nv_bfloat16* Ah, const __nv_bfloat16* Bh, int koff, int tid) {
    uint32_t sb = su + (uint32_t)stage * AV_STG;
    #pragma unroll
    for (int i = 0; i < 4; i++) {
        int idx = tid + 512 * i;
        int row = idx >> 3, seg = idx & 7;
        cp16(sb + (uint32_t)(row * AV_RS + seg * 16),
             Ah + (size_t)row * NN + koff + seg * 8);
    }
    #pragma unroll
    for (int i = 0; i < 2; i++) {
        int idx = tid + 512 * i;
        int row = idx >> 3, seg = idx & 7;
        cp16(sb + AV_AB + (uint32_t)(row * AV_RS + seg * 16),
             Bh + (size_t)row * NN + koff + seg * 8);
    }
    cp_commit();
}

__device__ __forceinline__ void av_compute(uint32_t su, int stage,
        int wm, int wn, int lane, float acc[4][4][4]) {
    uint32_t sb = su + (uint32_t)stage * AV_STG;
    int j = lane >> 3, r7 = lane & 7;
    uint32_t Ab = sb + (uint32_t)((wm * 64 + (j & 1) * 8 + r7) * AV_RS + (j >> 1) * 16);
    uint32_t Bb = sb + AV_AB + (uint32_t)((wn * 32 + (j >> 1) * 8 + r7) * AV_RS + (j & 1) * 16);
    #pragma unroll
    for (int kk = 0; kk < 4; kk++) {
        uint32_t ko = (uint32_t)(kk * 32);
        uint32_t ah[4][4], bh[2][4];
        #pragma unroll
        for (int mt = 0; mt < 4; mt++) ldsm4(ah[mt], Ab + (uint32_t)(mt * 16 * AV_RS) + ko);
        #pragma unroll
        for (int np = 0; np < 2; np++) ldsm4(bh[np], Bb + (uint32_t)(np * 16 * AV_RS) + ko);
        #pragma unroll
        for (int mt = 0; mt < 4; mt++)
            #pragma unroll
            for (int nt = 0; nt < 4; nt++) {
                int np = nt >> 1, o = (nt & 1) * 2;
                mma16816(acc[mt][nt], ah[mt], bh[np][o], bh[np][o + 1]);
            }
    }
}

__global__ __launch_bounds__(512, 1)
void gemm_av_mma(const float* __restrict__ x, const float* __restrict__ gamma,
                 float* __restrict__ out) {
    extern __shared__ __align__(16) char sm[];
    uint32_t su = smem_u32(sm);
    int b = blockIdx.z, m0 = blockIdx.x * 128, c0 = blockIdx.y * 256;
    const __nv_bfloat16* Ah = g_vh  + ((size_t)b * CC + c0) * NN;
    const __nv_bfloat16* Bh = g_pTh + ((size_t)b * NN + m0) * NN;
    int tid = threadIdx.x, lane = tid & 31, wid = tid >> 5;
    int wm = wid >> 2, wn = wid & 3;

    float* scinv = (float*)(sm + 2u * AV_STG);
    if (tid < 128) scinv[tid] = 1.0f / g_csum[b * NN + m0 + tid];

    float acc[4][4][4];
    #pragma unroll
    for (int i = 0; i < 4; i++)
        #pragma unroll
        for (int j = 0; j < 4; j++)
            #pragma unroll
            for (int e = 0; e < 4; e++) acc[i][j][e] = 0.f;

    const int NCH = NN / 64;   // 16
    av_issue(su, 0, Ah, Bh, 0, tid);
    for (int ch = 0; ch < NCH; ch++) {
        cp_wait0();
        __syncthreads();
        if (ch + 1 < NCH)
            av_issue(su, (ch + 1) & 1, Ah, Bh, (ch + 1) * 64, tid);
        av_compute(su, ch & 1, wm, wn, lane, acc);
    }

    float* fb = (float*)sm;
    float gm = *gamma;
    for (int h = 0; h < 2; h++) {
        __syncthreads();
        if ((wm >> 1) == h) {
            int rowbase = (wm & 1) * 64;
            int g = lane >> 2, t = lane & 3;
            #pragma unroll
            for (int mt = 0; mt < 4; mt++)
                #pragma unroll
                for (int nt = 0; nt < 4; nt++) {
                    float* p = fb + (rowbase + mt * 16 + g) * 132 + wn * 32 + nt * 8 + 2 * t;
                    p[0] = acc[mt][nt][0]; p[1] = acc[mt][nt][1];
                    p[8 * 132] = acc[mt][nt][2]; p[8 * 132 + 1] = acc[mt][nt][3];
                }
        }
        __syncthreads();
        #pragma unroll
        for (int j = 0; j < 8; j++) {
            int row = (tid >> 5) + j * 16;      // 0..127
            int c = c0 + h * 128 + row;
            int col = lane * 4;
            float4 d  = *reinterpret_cast<const float4*>(fb + row * 132 + col);
            float4 ci = *reinterpret_cast<const float4*>(scinv + col);
            size_t o = ((size_t)b * CC + c) * NN + m0 + col;
            float4 xv = *reinterpret_cast<const float4*>(x + o);
            float4 ov;
            ov.x = gm * ci.x * d.x + xv.x;
            ov.y = gm * ci.y * d.y + xv.y;
            ov.z = gm * ci.z * d.z + xv.z;
            ov.w = gm * ci.w * d.w + xv.w;
            *reinterpret_cast<float4*>(out + o) = ov;
        }
    }
}

// =================================================================
extern "C" void kernel_launch(void* const* d_in, const int* in_sizes, int n_in,
                              void* d_out, int out_size) {
    const float* x     = (const float*)d_in[0];
    const float* Wq    = (const float*)d_in[1];
    const float* bq    = (const float*)d_in[2];
    const float* uq    = (const float*)d_in[3];
    const float* Wk    = (const float*)d_in[4];
    const float* bk    = (const float*)d_in[5];
    const float* uk    = (const float*)d_in[6];
    const float* Wv    = (const float*)d_in[7];
    const float* bv    = (const float*)d_in[8];
    const float* uv    = (const float*)d_in[9];
    const float* gamma = (const float*)d_in[10];
    float* out = (float*)d_out;

    static int inited = 0;
    if (!inited) {
        cudaFuncSetAttribute(proj_qk_mma, cudaFuncAttributeMaxDynamicSharedMemorySize, SMEM_QKP);
        cudaFuncSetAttribute(proj_v_mma,  cudaFuncAttributeMaxDynamicSharedMemorySize, SMEM_PV);
        cudaFuncSetAttribute(gemm_qk_mma, cudaFuncAttributeMaxDynamicSharedMemorySize, SMEM_QKP);
        cudaFuncSetAttribute(gemm_av_mma, cudaFuncAttributeMaxDynamicSharedMemorySize, SMEM_AVN);
        inited = 1;
    }

    spectral_k<<<3, 512>>>(Wq, uq, Wk, uk, Wv, uv);
    prep_k<<<dim3(NN / 32, CC / 32, BB), dim3(32, 8)>>>(x, Wq, bq, Wk, bk, Wv, bv);
    proj_qk_mma<<<dim3(NN / 128, 1, BB), 256, SMEM_QKP>>>();
    proj_v_mma<<<dim3(NN / 128, CC / 128, BB), 256, SMEM_PV>>>();
    gemm_qk_mma<<<dim3(NN / 128, NN / 128, BB), 256, SMEM_QKP>>>();
    gemm_av_mma<<<dim3(NN / 128, CC / 256, BB), 512, SMEM_AVN>>>(x, gamma, out);
}

// round 14
// speedup vs baseline: 1.0386x; 1.0386x over previous
#include <cuda_runtime.h>
#include <cuda_bf16.h>
#include <cstdint>

#define BB 32
#define CC 512
#define NN 1024
#define CQ 64
#define MR 640

// ---------------- scratch (device globals; no cudaMalloc) ----------------
__device__ float g_scale[3];
__device__ float g_bcat[MR];
__device__ __align__(16) __nv_bfloat16 g_w2h[MR * CC];
__device__ __align__(16) __nv_bfloat16 g_w2l[MR * CC];
__device__ __align__(16) __nv_bfloat16 g_xTh[(size_t)BB * NN * CC];
__device__ __align__(16) __nv_bfloat16 g_xTl[(size_t)BB * NN * CC];
__device__ __align__(16) __nv_bfloat16 g_qTh[(size_t)BB * NN * CQ];
__device__ __align__(16) __nv_bfloat16 g_qTl[(size_t)BB * NN * CQ];
__device__ __align__(16) __nv_bfloat16 g_kTh[(size_t)BB * NN * CQ];
__device__ __align__(16) __nv_bfloat16 g_kTl[(size_t)BB * NN * CQ];
__device__ __align__(16) __nv_bfloat16 g_vh [(size_t)BB * CC * NN];
__device__ __align__(16) __nv_bfloat16 g_pTh[(size_t)BB * NN * NN];
__device__ float g_csum[BB * NN];

// ---------------- helpers ----------------
__device__ __forceinline__ uint32_t smem_u32(const void* p) {
    uint32_t a;
    asm("{ .reg .u64 t; cvta.to.shared.u64 t, %1; cvt.u32.u64 %0, t; }" : "=r"(a) : "l"(p));
    return a;
}
__device__ __forceinline__ void cp16(uint32_t s, const void* g) {
    asm volatile("cp.async.cg.shared.global [%0], [%1], 16;" :: "r"(s), "l"(g));
}
__device__ __forceinline__ void cp_commit() { asm volatile("cp.async.commit_group;" ::: "memory"); }
__device__ __forceinline__ void cp_wait1()  { asm volatile("cp.async.wait_group 1;" ::: "memory"); }
__device__ __forceinline__ void cp_wait0()  { asm volatile("cp.async.wait_group 0;" ::: "memory"); }

__device__ __forceinline__ void ldsm4(uint32_t r[4], uint32_t addr) {
    asm volatile("ldmatrix.sync.aligned.m8n8.x4.shared.b16 {%0,%1,%2,%3}, [%4];"
        : "=r"(r[0]), "=r"(r[1]), "=r"(r[2]), "=r"(r[3]) : "r"(addr));
}

__device__ __forceinline__ void mma16816(float* c, const uint32_t a[4], uint32_t b0, uint32_t b1) {
    asm volatile(
        "mma.sync.aligned.m16n8k16.row.col.f32.bf16.bf16.f32 "
        "{%0,%1,%2,%3}, {%4,%5,%6,%7}, {%8,%9}, {%0,%1,%2,%3};"
        : "+f"(c[0]), "+f"(c[1]), "+f"(c[2]), "+f"(c[3])
        : "r"(a[0]), "r"(a[1]), "r"(a[2]), "r"(a[3]), "r"(b0), "r"(b1));
}

__device__ __forceinline__ void split2(float f, __nv_bfloat16& h, __nv_bfloat16& l) {
    h = __float2bfloat16(f);
    l = __float2bfloat16(f - __bfloat162float(h));
}
__device__ __forceinline__ uint32_t packbf(__nv_bfloat16 a, __nv_bfloat16 b) {
    __nv_bfloat162 t(a, b);
    return *reinterpret_cast<uint32_t*>(&t);
}

// ---------------- generic GEMM core: 128x128 tile, K-chunk 32 ----------------
#define ARR_B   10240u
#define SMEM_QKP (2u * 4u * ARR_B)   // 81920: proj_qk / QK (P=3, S=2)
#define SMEM_PV  (3u * 3u * ARR_B)   // 92160: proj_v (P=2, S=3)

template<int P>
__device__ __forceinline__ void issue_chunk(uint32_t su, int stage,
        const __nv_bfloat16* Ah, const __nv_bfloat16* Al, int lda,
        const __nv_bfloat16* Bh, const __nv_bfloat16* Bl, int ldb,
        int koff, int tid) {
    const uint32_t STG  = (P == 3 ? 4u : 3u) * ARR_B;
    const uint32_t OFFB = 2u * ARR_B;
    uint32_t sb = su + (uint32_t)stage * STG;
    int row = tid >> 2, seg = tid & 3;
    uint32_t so  = (uint32_t)(row * 80 + seg * 16);
    uint32_t so2 = (uint32_t)((row + 64) * 80 + seg * 16);
    size_t go  = (size_t)row * lda + koff + seg * 8;
    size_t go2 = (size_t)(row + 64) * lda + koff + seg * 8;
    cp16(sb + so,  Ah + go);
    cp16(sb + so2, Ah + go2);
    cp16(sb + ARR_B + so,  Al + go);
    cp16(sb + ARR_B + so2, Al + go2);
    size_t gb  = (size_t)row * ldb + koff + seg * 8;
    size_t gb2 = (size_t)(row + 64) * ldb + koff + seg * 8;
    cp16(sb + OFFB + so,  Bh + gb);
    cp16(sb + OFFB + so2, Bh + gb2);
    if (P == 3) {
        cp16(sb + OFFB + ARR_B + so,  Bl + gb);
        cp16(sb + OFFB + ARR_B + so2, Bl + gb2);
    }
    cp_commit();
}

template<int P>
__device__ __forceinline__ void compute_chunk(uint32_t su, int stage,
        int wm, int wn, int lane, float acc[4][4][4]) {
    const uint32_t STG  = (P == 3 ? 4u : 3u) * ARR_B;
    const uint32_t OFFB = 2u * ARR_B;
    uint32_t sb = su + (uint32_t)stage * STG;
    int j = lane >> 3, r7 = lane & 7;
    uint32_t Ab = sb + (uint32_t)((wm * 64 + (j & 1) * 8 + r7) * 80 + (j >> 1) * 16);
    uint32_t Bb = sb + OFFB + (uint32_t)((wn * 32 + (j >> 1) * 8 + r7) * 80 + (j & 1) * 16);
    #pragma unroll
    for (int kk = 0; kk < 2; kk++) {
        uint32_t ko = (uint32_t)(kk * 32);
        uint32_t ah[4][4], al[4][4], bh[2][4], bl[2][4];
        #pragma unroll
        for (int mt = 0; mt < 4; mt++) ldsm4(ah[mt], Ab + (uint32_t)(mt * 1280) + ko);
        #pragma unroll
        for (int mt = 0; mt < 4; mt++) ldsm4(al[mt], Ab + ARR_B + (uint32_t)(mt * 1280) + ko);
        #pragma unroll
        for (int np = 0; np < 2; np++) ldsm4(bh[np], Bb + (uint32_t)(np * 1280) + ko);
        if (P == 3) {
            #pragma unroll
            for (int np = 0; np < 2; np++) ldsm4(bl[np], Bb + ARR_B + (uint32_t)(np * 1280) + ko);
        }
        #pragma unroll
        for (int mt = 0; mt < 4; mt++)
            #pragma unroll
            for (int nt = 0; nt < 4; nt++) {
                int np = nt >> 1, o = (nt & 1) * 2;
                float* C = acc[mt][nt];
                mma16816(C, ah[mt], bh[np][o], bh[np][o + 1]);
                mma16816(C, al[mt], bh[np][o], bh[np][o + 1]);
                if (P == 3) mma16816(C, ah[mt], bl[np][o], bl[np][o + 1]);
            }
    }
}

template<int P, int S>
__device__ __forceinline__ void run_gemm(uint32_t su,
        const __nv_bfloat16* Ah, const __nv_bfloat16* Al, int lda,
        const __nv_bfloat16* Bh, const __nv_bfloat16* Bl, int ldb,
        int nch, float acc[4][4][4]) {
    int tid = threadIdx.x, lane = tid & 31, wid = tid >> 5;
    int wm = wid >> 2, wn = wid & 3;
    #pragma unroll
    for (int i = 0; i < 4; i++)
        #pragma unroll
        for (int j = 0; j < 4; j++)
            #pragma unroll
            for (int e = 0; e < 4; e++) acc[i][j][e] = 0.f;

    #pragma unroll
    for (int s = 0; s < S - 1; s++)
        issue_chunk<P>(su, s, Ah, Al, lda, Bh, Bl, ldb, s * 32, tid);

    for (int ch = 0; ch < nch; ch++) {
        if (S == 2) { cp_wait0(); }
        else        { if (ch == nch - 1) cp_wait0(); else cp_wait1(); }
        __syncthreads();
        int nx = ch + S - 1;
        if (nx < nch)
            issue_chunk<P>(su, nx % S, Ah, Al, lda, Bh, Bl, ldb, nx * 32, tid);
        compute_chunk<P>(su, ch % S, wm, wn, lane, acc);
    }
    __syncthreads();
}

// Stage one 64-row half of the 128x128 fp32 result into smem (stride 132).
__device__ __forceinline__ void stage_half(float* fb, int h, float acc[4][4][4]) {
    int tid = threadIdx.x, lane = tid & 31, wid = tid >> 5;
    int wm = wid >> 2, wn = wid & 3;
    if (wm != h) return;
    int g = lane >> 2, t = lane & 3;
    #pragma unroll
    for (int mt = 0; mt < 4; mt++)
        #pragma unroll
        for (int nt = 0; nt < 4; nt++) {
            float* p = fb + (mt * 16 + g) * 132 + wn * 32 + nt * 8 + 2 * t;
            p[0] = acc[mt][nt][0]; p[1] = acc[mt][nt][1];
            p[8 * 132] = acc[mt][nt][2]; p[8 * 132 + 1] = acc[mt][nt][3];
        }
}

// =================================================================
// Spectral norm (fp32)
// =================================================================
__global__ void spectral_k(const float* __restrict__ Wq, const float* __restrict__ uq,
                           const float* __restrict__ Wk, const float* __restrict__ uk,
                           const float* __restrict__ Wv, const float* __restrict__ uv) {
    const float* W; const float* u; int out;
    if (blockIdx.x == 0)      { W = Wq; u = uq; out = CQ; }
    else if (blockIdx.x == 1) { W = Wk; u = uk; out = CQ; }
    else                      { W = Wv; u = uv; out = CC; }
    const int in = CC;
    __shared__ float sv[CC];
    __shared__ float st[CC];
    __shared__ float red[16];
    int tid = threadIdx.x, lane = tid & 31, w = tid >> 5;

    float acc = 0.f;
    for (int i = 0; i < out; i++) acc += W[i * in + tid] * u[i];
    sv[tid] = acc;

    float s = acc * acc;
    #pragma unroll
    for (int o = 16; o; o >>= 1) s += __shfl_xor_sync(0xffffffffu, s, o);
    if (lane == 0) red[w] = s;
    __syncthreads();
    if (tid < 16) {
        float r = red[tid];
        #pragma unroll
        for (int o = 8; o; o >>= 1) r += __shfl_xor_sync(0xffffu, r, o);
        if (tid == 0) red[0] = r;
    }
    __syncthreads();
    float inv = rsqrtf(red[0]);
    __syncthreads();

    for (int i = w; i < out; i += 16) {
        float a = 0.f;
        for (int jj = lane; jj < in; jj += 32) a += W[i * in + jj] * sv[jj];
        #pragma unroll
        for (int o = 16; o; o >>= 1) a += __shfl_xor_sync(0xffffffffu, a, o);
        if (lane == 0) st[i] = a * inv;
    }
    __syncthreads();

    float q = (tid < out) ? st[tid] * st[tid] : 0.f;
    #pragma unroll
    for (int o = 16; o; o >>= 1) q += __shfl_xor_sync(0xffffffffu, q, o);
    if (lane == 0) red[w] = q;
    __syncthreads();
    if (tid == 0) {
        float r = 0.f;
        #pragma unroll
        for (int i = 0; i < 16; i++) r += red[i];
        g_scale[blockIdx.x] = rsqrtf(r);
    }
}

// =================================================================
// prep: fused build_w2k + xsplit (+ zero csum).
// =================================================================
__global__ void prep_k(const float* __restrict__ x,
                       const float* __restrict__ Wq, const float* __restrict__ bq,
                       const float* __restrict__ Wk, const float* __restrict__ bk,
                       const float* __restrict__ Wv, const float* __restrict__ bv) {
    int tx = threadIdx.x, ty = threadIdx.y;
    int tid = ty * 32 + tx;
    int flat = (blockIdx.z * 16 + blockIdx.y) * 32 + blockIdx.x;

    if (flat < (MR * CC) / 256) {
        int idx = flat * 256 + tid;
        if (idx < BB * NN) g_csum[idx] = 0.f;
        int r = idx >> 9, c = idx & (CC - 1);
        float wv, sc;
        if (r < CQ)          { wv = Wq[r * CC + c];            sc = g_scale[0]; }
        else if (r < 2 * CQ) { wv = Wk[(r - CQ) * CC + c];     sc = g_scale[1]; }
        else                 { wv = Wv[(r - 2 * CQ) * CC + c]; sc = g_scale[2]; }
        __nv_bfloat16 h, l;
        split2(wv * sc, h, l);
        g_w2h[idx] = h; g_w2l[idx] = l;
        if (c == 0)
            g_bcat[r] = (r < CQ) ? bq[r] : (r < 2 * CQ ? bk[r - CQ] : bv[r - 2 * CQ]);
    }

    __shared__ float t[32][33];
    int b = blockIdx.z, n0 = blockIdx.x * 32, c0 = blockIdx.y * 32;
    const float* xb = x + (size_t)b * CC * NN;
    #pragma unroll
    for (int j = 0; j < 4; j++)
        t[ty + 8 * j][tx] = xb[(size_t)(c0 + ty + 8 * j) * NN + n0 + tx];
    __syncthreads();
    #pragma unroll
    for (int j = 0; j < 4; j++) {
        int n = n0 + ty + 8 * j;
        __nv_bfloat16 h, l;
        split2(t[tx][ty + 8 * j], h, l);
        size_t o = ((size_t)b * NN + n) * CC + c0 + tx;
        g_xTh[o] = h; g_xTl[o] = l;
    }
}

// =================================================================
// proj_qk (P=3,S=2): D[n][r] = xT[n]·w[r] + b[r] -> qT/kT hi/lo [b][n][64]
// =================================================================
__global__ __launch_bounds__(256, 2)
void proj_qk_mma(void) {
    extern __shared__ __align__(16) char sm[];
    uint32_t su = smem_u32(sm);
    int b = blockIdx.z, n0 = blockIdx.x * 128;
    const __nv_bfloat16* Ah = g_xTh + ((size_t)b * NN + n0) * CC;
    const __nv_bfloat16* Al = g_xTl + ((size_t)b * NN + n0) * CC;
    float acc[4][4][4];
    run_gemm<3, 2>(su, Ah, Al, CC, g_w2h, g_w2l, CC, CC / 32, acc);

    float* fb = (float*)sm;
    int tid = threadIdx.x, lane = tid & 31;
    for (int h = 0; h < 2; h++) {
        __syncthreads();
        stage_half(fb, h, acc);
        __syncthreads();
        #pragma unroll
        for (int j = 0; j < 8; j++) {
            int r = (tid >> 5) + j * 8;
            int n = n0 + h * 64 + r;
            int rr = lane * 4;
            const float* p = fb + r * 132 + rr;
            uint32_t hp[2], lp[2];
            #pragma unroll
            for (int e = 0; e < 2; e++) {
                float f0 = p[2 * e]     + g_bcat[rr + 2 * e];
                float f1 = p[2 * e + 1] + g_bcat[rr + 2 * e + 1];
                __nv_bfloat16 h0, l0, h1, l1;
                split2(f0, h0, l0); split2(f1, h1, l1);
                hp[e] = packbf(h0, h1); lp[e] = packbf(l0, l1);
            }
            size_t o;
            __nv_bfloat16 *dh, *dl;
            if (rr < 64) { o = ((size_t)b * NN + n) * CQ + rr;      dh = g_qTh; dl = g_qTl; }
            else         { o = ((size_t)b * NN + n) * CQ + rr - 64; dh = g_kTh; dl = g_kTl; }
            *reinterpret_cast<uint2*>(dh + o) = *reinterpret_cast<uint2*>(hp);
            *reinterpret_cast<uint2*>(dl + o) = *reinterpret_cast<uint2*>(lp);
        }
    }
}

// =================================================================
// proj_v (P=2,S=3): D[c][n] = (wh+wl)[c]·xh[n] + bv[c] -> v bf16 [b][c][n]
// =================================================================
__global__ __launch_bounds__(256, 2)
void proj_v_mma(void) {
    extern __shared__ __align__(16) char sm[];
    uint32_t su = smem_u32(sm);
    int b = blockIdx.z, n0 = blockIdx.x * 128, c0 = blockIdx.y * 128;
    const __nv_bfloat16* Ah = g_w2h + (size_t)(2 * CQ + c0) * CC;
    const __nv_bfloat16* Al = g_w2l + (size_t)(2 * CQ + c0) * CC;
    const __nv_bfloat16* Bh = g_xTh + ((size_t)b * NN + n0) * CC;
    float acc[4][4][4];
    run_gemm<2, 3>(su, Ah, Al, CC, Bh, (const __nv_bfloat16*)0, CC, CC / 32, acc);

    float* fb = (float*)sm;
    int tid = threadIdx.x, lane = tid & 31;
    for (int h = 0; h < 2; h++) {
        __syncthreads();
        stage_half(fb, h, acc);
        __syncthreads();
        #pragma unroll
        for (int j = 0; j < 8; j++) {
            int r = (tid >> 5) + j * 8;
            int c = c0 + h * 64 + r;
            float bias = g_bcat[2 * CQ + c];
            const float* p = fb + r * 132 + lane * 4;
            uint32_t hp[2];
            #pragma unroll
            for (int e = 0; e < 2; e++) {
                __nv_bfloat16 h0 = __float2bfloat16(p[2 * e] + bias);
                __nv_bfloat16 h1 = __float2bfloat16(p[2 * e + 1] + bias);
                hp[e] = packbf(h0, h1);
            }
            size_t o = ((size_t)b * CC + c) * NN + n0 + lane * 4;
            *reinterpret_cast<uint2*>(g_vh + o) = *reinterpret_cast<uint2*>(hp);
        }
    }
}

// =================================================================
// QK (P=3,S=2): D[m][n] = kT[m]·qT[n]; pT = bf16(exp(D)); csum += rounded sums
// =================================================================
__global__ __launch_bounds__(256, 2)
void gemm_qk_mma(void) {
    extern __shared__ __align__(16) char sm[];
    uint32_t su = smem_u32(sm);
    int b = blockIdx.z, m0 = blockIdx.y * 128, n0 = blockIdx.x * 128;
    const __nv_bfloat16* Ah = g_kTh + ((size_t)b * NN + m0) * CQ;
    const __nv_bfloat16* Al = g_kTl + ((size_t)b * NN + m0) * CQ;
    const __nv_bfloat16* Bh = g_qTh + ((size_t)b * NN + n0) * CQ;
    const __nv_bfloat16* Bl = g_qTl + ((size_t)b * NN + n0) * CQ;
    float acc[4][4][4];
    run_gemm<3, 2>(su, Ah, Al, CQ, Bh, Bl, CQ, CQ / 32, acc);

    float* fb = (float*)sm;
    int tid = threadIdx.x, lane = tid & 31;
    for (int h = 0; h < 2; h++) {
        __syncthreads();
        stage_half(fb, h, acc);
        __syncthreads();
        #pragma unroll
        for (int j = 0; j < 8; j++) {
            int r = (tid >> 5) + j * 8;
            int m = m0 + h * 64 + r;
            const float* p = fb + r * 132 + lane * 4;
            uint32_t hp[2];
            float rs = 0.f;
            #pragma unroll
            for (int e = 0; e < 2; e++) {
                __nv_bfloat16 h0 = __float2bfloat16(__expf(p[2 * e]));
                __nv_bfloat16 h1 = __float2bfloat16(__expf(p[2 * e + 1]));
                rs += __bfloat162float(h0) + __bfloat162float(h1);
                hp[e] = packbf(h0, h1);
            }
            size_t o = ((size_t)b * NN + m) * NN + n0 + lane * 4;
            *reinterpret_cast<uint2*>(g_pTh + o) = *reinterpret_cast<uint2*>(hp);
            #pragma unroll
            for (int of = 16; of; of >>= 1) rs += __shfl_xor_sync(0xffffffffu, rs, of);
            if (lane == 0) atomicAdd(&g_csum[b * NN + m], rs);
        }
    }
}

// =================================================================
// AV: 512 threads, tile 256(c) x 128(m), K-chunk 64, S=2, P=1. Fused cinv.
// =================================================================
#define AV_RS   144u
#define AV_AB   (256u * AV_RS)
#define AV_STG  (AV_AB + 128u * AV_RS)
#define SMEM_AVN (2u * AV_STG + 512u)

__device__ __forceinline__ void av_issue(uint32_t su, int stage,
        const __nv_bfloat16* Ah, const __nv_bfloat16* Bh, int koff, int tid) {
    uint32_t sb = su + (uint32_t)stage * AV_STG;
    #pragma unroll
    for (int i = 0; i < 4; i++) {
        int idx = tid + 512 * i;
        int row = idx >> 3, seg = idx & 7;
        cp16(sb + (uint32_t)(row * AV_RS + seg * 16),
             Ah + (size_t)row * NN + koff + seg * 8);
    }
    #pragma unroll
    for (int i = 0; i < 2; i++) {
        int idx = tid + 512 * i;
        int row = idx >> 3, seg = idx & 7;
        cp16(sb + AV_AB + (uint32_t)(row * AV_RS + seg * 16),
             Bh + (size_t)row * NN + koff + seg * 8);
    }
    cp_commit();
}

__device__ __forceinline__ void av_compute(uint32_t su, int stage,
        int wm, int wn, int lane, float acc[4][4][4]) {
    uint32_t sb = su + (uint32_t)stage * AV_STG;
    int j = lane >> 3, r7 = lane & 7;
    uint32_t Ab = sb + (uint32_t)((wm * 64 + (j & 1) * 8 + r7) * AV_RS + (j >> 1) * 16);
    uint32_t Bb = sb + AV_AB + (uint32_t)((wn * 32 + (j >> 1) * 8 + r7) * AV_RS + (j & 1) * 16);
    #pragma unroll
    for (int kk = 0; kk < 4; kk++) {
        uint32_t ko = (uint32_t)(kk * 32);
        uint32_t ah[4][4], bh[2][4];
        #pragma unroll
        for (int mt = 0; mt < 4; mt++) ldsm4(ah[mt], Ab + (uint32_t)(mt * 16 * AV_RS) + ko);
        #pragma unroll
        for (int np = 0; np < 2; np++) ldsm4(bh[np], Bb + (uint32_t)(np * 16 * AV_RS) + ko);
        #pragma unroll
        for (int mt = 0; mt < 4; mt++)
            #pragma unroll
            for (int nt = 0; nt < 4; nt++) {
                int np = nt >> 1, o = (nt & 1) * 2;
                mma16816(acc[mt][nt], ah[mt], bh[np][o], bh[np][o + 1]);
            }
    }
}

__global__ __launch_bounds__(512, 1)
void gemm_av_mma(const float* __restrict__ x, const float* __restrict__ gamma,
                 float* __restrict__ out) {
    extern __shared__ __align__(16) char sm[];
    uint32_t su = smem_u32(sm);
    int b = blockIdx.z, m0 = blockIdx.x * 128, c0 = blockIdx.y * 256;
    const __nv_bfloat16* Ah = g_vh  + ((size_t)b * CC + c0) * NN;
    const __nv_bfloat16* Bh = g_pTh + ((size_t)b * NN + m0) * NN;
    int tid = threadIdx.x, lane = tid & 31, wid = tid >> 5;
    int wm = wid >> 2, wn = wid & 3;

    float* scinv = (float*)(sm + 2u * AV_STG);
    if (tid < 128) scinv[tid] = 1.0f / g_csum[b * NN + m0 + tid];

    float acc[4][4][4];
    #pragma unroll
    for (int i = 0; i < 4; i++)
        #pragma unroll
        for (int j = 0; j < 4; j++)
            #pragma unroll
            for (int e = 0; e < 4; e++) acc[i][j][e] = 0.f;

    const int NCH = NN / 64;
    av_issue(su, 0, Ah, Bh, 0, tid);
    for (int ch = 0; ch < NCH; ch++) {
        cp_wait0();
        __syncthreads();
        if (ch + 1 < NCH)
            av_issue(su, (ch + 1) & 1, Ah, Bh, (ch + 1) * 64, tid);
        av_compute(su, ch & 1, wm, wn, lane, acc);
    }

    float* fb = (float*)sm;
    float gm = *gamma;
    for (int h = 0; h < 2; h++) {
        __syncthreads();
        if ((wm >> 1) == h) {
            int rowbase = (wm & 1) * 64;
            int g = lane >> 2, t = lane & 3;
            #pragma unroll
            for (int mt = 0; mt < 4; mt++)
                #pragma unroll
                for (int nt = 0; nt < 4; nt++) {
                    float* p = fb + (rowbase + mt * 16 + g) * 132 + wn * 32 + nt * 8 + 2 * t;
                    p[0] = acc[mt][nt][0]; p[1] = acc[mt][nt][1];
                    p[8 * 132] = acc[mt][nt][2]; p[8 * 132 + 1] = acc[mt][nt][3];
                }
        }
        __syncthreads();
        #pragma unroll
        for (int j = 0; j < 8; j++) {
            int row = (tid >> 5) + j * 16;
            int c = c0 + h * 128 + row;
            int col = lane * 4;
            float4 d  = *reinterpret_cast<const float4*>(fb + row * 132 + col);
            float4 ci = *reinterpret_cast<const float4*>(scinv + col);
            size_t o = ((size_t)b * CC + c) * NN + m0 + col;
            float4 xv = *reinterpret_cast<const float4*>(x + o);
            float4 ov;
            ov.x = gm * ci.x * d.x + xv.x;
            ov.y = gm * ci.y * d.y + xv.y;
            ov.z = gm * ci.z * d.z + xv.z;
            ov.w = gm * ci.w * d.w + xv.w;
            *reinterpret_cast<float4*>(out + o) = ov;
        }
    }
}

// =================================================================
extern "C" void kernel_launch(void* const* d_in, const int* in_sizes, int n_in,
                              void* d_out, int out_size) {
    const float* x     = (const float*)d_in[0];
    const float* Wq    = (const float*)d_in[1];
    const float* bq    = (const float*)d_in[2];
    const float* uq    = (const float*)d_in[3];
    const float* Wk    = (const float*)d_in[4];
    const float* bk    = (const float*)d_in[5];
    const float* uk    = (const float*)d_in[6];
    const float* Wv    = (const float*)d_in[7];
    const float* bv    = (const float*)d_in[8];
    const float* uv    = (const float*)d_in[9];
    const float* gamma = (const float*)d_in[10];
    float* out = (float*)d_out;

    static int inited = 0;
    static cudaStream_t sA, sB;
    static cudaEvent_t eRoot, eA, eB;
    if (!inited) {
        cudaFuncSetAttribute(proj_qk_mma, cudaFuncAttributeMaxDynamicSharedMemorySize, SMEM_QKP);
        cudaFuncSetAttribute(proj_v_mma,  cudaFuncAttributeMaxDynamicSharedMemorySize, SMEM_PV);
        cudaFuncSetAttribute(gemm_qk_mma, cudaFuncAttributeMaxDynamicSharedMemorySize, SMEM_QKP);
        cudaFuncSetAttribute(gemm_av_mma, cudaFuncAttributeMaxDynamicSharedMemorySize, SMEM_AVN);
        cudaStreamCreateWithFlags(&sA, cudaStreamNonBlocking);
        cudaStreamCreateWithFlags(&sB, cudaStreamNonBlocking);
        cudaEventCreateWithFlags(&eRoot, cudaEventDisableTiming);
        cudaEventCreateWithFlags(&eA,    cudaEventDisableTiming);
        cudaEventCreateWithFlags(&eB,    cudaEventDisableTiming);
        inited = 1;
    }

    // chain: spectral -> prep on the capture (default) stream
    spectral_k<<<3, 512>>>(Wq, uq, Wk, uk, Wv, uv);
    prep_k<<<dim3(NN / 32, CC / 32, BB), dim3(32, 8)>>>(x, Wq, bq, Wk, bk, Wv, bv);

    // fork
    cudaEventRecord(eRoot, 0);
    cudaStreamWaitEvent(sA, eRoot, 0);
    cudaStreamWaitEvent(sB, eRoot, 0);

    // stream A: proj_qk -> QK ; stream B: proj_v (independent, overlaps)
    proj_qk_mma<<<dim3(NN / 128, 1, BB), 256, SMEM_QKP, sA>>>();
    gemm_qk_mma<<<dim3(NN / 128, NN / 128, BB), 256, SMEM_QKP, sA>>>();
    proj_v_mma <<<dim3(NN / 128, CC / 128, BB), 256, SMEM_PV,  sB>>>();

    // join
    cudaEventRecord(eA, sA);
    cudaEventRecord(eB, sB);
    cudaStreamWaitEvent(0, eA, 0);
    cudaStreamWaitEvent(0, eB, 0);

    gemm_av_mma<<<dim3(NN / 128, CC / 256, BB), 512, SMEM_AVN>>>(x, gamma, out);
}